// round 7
// baseline (speedup 1.0000x reference)
#include <cuda_runtime.h>
#include <cstdint>

// D-FPS (B=8, N=32768, npoint=2048) + gather xyz -> out (B,3,2048) fp32.
//
// One 16-CTA cluster per batch (nonportable cluster size; 128 CTAs total,
// 512 threads each). Each thread owns 4 points, PACKED f32x2 in registers;
// running-min temp in registers. Per iteration:
//   - packed add/mul.rn.f32x2 distance update (per-lane .rn => bit-exact)
//   - warp argmax via redux.sync (float bits of v>=0 are u32-monotone),
//     min-index tie-break == jnp.argmax first-occurrence
//   - CTA argmax in warp0 via redux; lanes 0..15 push {key,x,y,z} to cluster
//     CTA dst==lane in parallel (mapa + st.shared::cluster); winner coords
//     come from a CTA-local smem coord table (LDS, not L2)
//   - ONE barrier.cluster (arrive releases the remote stores, wait acquires)
//   - every thread picks the cluster winner from its own 16 smem slots via a
//     depth-4 max tree.
// Slots double-buffered by parity: a same-parity overwrite for iter j+2 can
// only be issued after the cluster barrier of iter j+1, which post-dates all
// reads of the iter-j slots.

constexpr int BATCH   = 8;
constexpr int NPTS    = 32768;
constexpr int NPOINT  = 2048;
constexpr int CLUSTER = 16;
constexpr int T       = 512;
constexpr int PER_CTA = NPTS / CLUSTER;  // 2048
constexpr int P       = PER_CTA / T;     // 4 points / thread
constexpr int NPAIR   = P / 2;           // 2 packed pairs
constexpr int NW      = T / 32;          // 16 warps

__device__ __forceinline__ uint32_t smem_u32(const void* p) {
    uint32_t a;
    asm("{ .reg .u64 t; cvta.to.shared.u64 t, %1; cvt.u32.u64 %0, t; }"
        : "=r"(a) : "l"(p));
    return a;
}

extern __shared__ float s_dyn[];  // sx[2048] | sy[2048] | sz[2048] = 24KB

__global__ __launch_bounds__(T, 1)
void fps_cluster_kernel(const float* __restrict__ xyz_t, float* __restrict__ out)
{
    const int b = blockIdx.x / CLUSTER;
    uint32_t rank;
    asm("mov.u32 %0, %%cluster_ctarank;" : "=r"(rank));

    const float* __restrict__ xs = xyz_t + (size_t)b * 3 * NPTS;
    const float* __restrict__ ys = xs + NPTS;
    const float* __restrict__ zs = xs + 2 * NPTS;
    float* __restrict__ ob = out + (size_t)b * 3 * NPOINT;

    const int tid = threadIdx.x;
    const int w = tid >> 5, l = tid & 31;
    const int pbase = (int)rank * PER_CTA;

    float* sx = s_dyn;
    float* sy = s_dyn + PER_CTA;
    float* sz = s_dyn + 2 * PER_CTA;

    __shared__ uint32_t s_wv[NW], s_wi[NW];
    __shared__ unsigned long long s_key[2][CLUSTER];
    __shared__ float4 s_co[2][CLUSTER];

    // ---- load coords: smem table + packed registers ----
    unsigned long long xp[NPAIR], yp[NPAIR], zp[NPAIR];
    float tmp[P];
    {
        float a[P], c[P], d[P];
#pragma unroll
        for (int i = 0; i < P; ++i) {
            const int g = pbase + i * T + tid;
            a[i] = xs[g]; c[i] = ys[g]; d[i] = zs[g];
            sx[i * T + tid] = a[i];
            sy[i * T + tid] = c[i];
            sz[i * T + tid] = d[i];
            tmp[i] = 1e10f;
        }
#pragma unroll
        for (int q = 0; q < NPAIR; ++q) {
            asm("mov.b64 %0, {%1, %2};" : "=l"(xp[q]) : "f"(a[2*q]), "f"(a[2*q+1]));
            asm("mov.b64 %0, {%1, %2};" : "=l"(yp[q]) : "f"(c[2*q]), "f"(c[2*q+1]));
            asm("mov.b64 %0, {%1, %2};" : "=l"(zp[q]) : "f"(d[2*q]), "f"(d[2*q+1]));
        }
    }

    float lx = __ldg(xs), ly = __ldg(ys), lz = __ldg(zs);  // idx[0] = 0
    if (rank == 0 && tid == 0) {
        ob[0] = lx; ob[NPOINT] = ly; ob[2 * NPOINT] = lz;
    }

    for (int j = 1; j < NPOINT; ++j) {
        // packed negated center (per-lane duplicate)
        unsigned long long nlx2, nly2, nlz2;
        {
            const float nx = -lx, ny = -ly, nz = -lz;
            asm("mov.b64 %0, {%1, %1};" : "=l"(nlx2) : "f"(nx));
            asm("mov.b64 %0, {%1, %1};" : "=l"(nly2) : "f"(ny));
            asm("mov.b64 %0, {%1, %1};" : "=l"(nlz2) : "f"(nz));
        }

        float bv = -1.0f;
        int   bs = 0;
#pragma unroll
        for (int q = 0; q < NPAIR; ++q) {
            unsigned long long dx, dy, dz, qx, qy, qz, s01, acc;
            asm("add.rn.f32x2 %0, %1, %2;" : "=l"(dx) : "l"(xp[q]), "l"(nlx2));
            asm("add.rn.f32x2 %0, %1, %2;" : "=l"(dy) : "l"(yp[q]), "l"(nly2));
            asm("add.rn.f32x2 %0, %1, %2;" : "=l"(dz) : "l"(zp[q]), "l"(nlz2));
            asm("mul.rn.f32x2 %0, %1, %1;" : "=l"(qx) : "l"(dx));
            asm("mul.rn.f32x2 %0, %1, %1;" : "=l"(qy) : "l"(dy));
            asm("mul.rn.f32x2 %0, %1, %1;" : "=l"(qz) : "l"(dz));
            asm("add.rn.f32x2 %0, %1, %2;" : "=l"(s01) : "l"(qx), "l"(qy));
            asm("add.rn.f32x2 %0, %1, %2;" : "=l"(acc) : "l"(s01), "l"(qz));
            float d0, d1;
            asm("mov.b64 {%0, %1}, %2;" : "=f"(d0), "=f"(d1) : "l"(acc));
            float t0 = fminf(tmp[2*q], d0);     tmp[2*q] = t0;
            if (t0 > bv) { bv = t0; bs = 2*q; }
            float t1 = fminf(tmp[2*q+1], d1);   tmp[2*q+1] = t1;
            if (t1 > bv) { bv = t1; bs = 2*q+1; }
        }
        const uint32_t idx = (uint32_t)(pbase + bs * T + tid);

        // ---- warp argmax via redux (float bits of v>=0 are u32-monotone) ----
        const uint32_t vb   = __float_as_uint(bv);
        const uint32_t vmax = __reduce_max_sync(0xffffffffu, vb);
        const uint32_t imin = __reduce_min_sync(0xffffffffu,
                                   (vb == vmax) ? idx : 0xffffffffu);
        if (l == 0) { s_wv[w] = vmax; s_wi[w] = imin; }
        __syncthreads();

        const int p = j & 1;

        if (w == 0) {
            const uint32_t v  = (l < NW) ? s_wv[l] : 0u;
            const uint32_t ii = (l < NW) ? s_wi[l] : 0xffffffffu;
            const uint32_t vm = __reduce_max_sync(0xffffffffu, v);
            const uint32_t im = __reduce_min_sync(0xffffffffu,
                                    (v == vm) ? ii : 0xffffffffu);
            // redux leaves the result in every lane: lanes 0..15 disseminate
            // to cluster CTA dst == lane, in parallel.
            if (l < CLUSTER) {
                const int li = (int)im - pbase;      // winner is in own range
                const float cx = sx[li], cy = sy[li], cz = sz[li];  // LDS bcast
                const unsigned long long key =
                    ((unsigned long long)vm << 32) | (uint32_t)(~im);
                unsigned long long xyp;
                asm("mov.b64 %0, {%1, %2};" : "=l"(xyp) : "f"(cx), "f"(cy));
                const uint32_t zb = __float_as_uint(cz);
                const uint32_t ka = smem_u32(&s_key[p][rank]);
                const uint32_t ca = smem_u32(&s_co[p][rank]);
                const int dco = (int)(ca - ka);
                uint32_t rk;
                asm volatile("mapa.shared::cluster.u32 %0, %1, %2;"
                             : "=r"(rk) : "r"(ka), "r"(l));
                asm volatile("st.shared::cluster.b64 [%0], %1;"
                             :: "r"(rk), "l"(key) : "memory");
                asm volatile("st.shared::cluster.b64 [%0], %1;"
                             :: "r"(rk + dco), "l"(xyp) : "memory");
                asm volatile("st.shared::cluster.b32 [%0+8], %1;"
                             :: "r"(rk + dco), "r"(zb) : "memory");
            }
        }

        // arrive = release (orders the shared::cluster stores), wait = acquire
        asm volatile("barrier.cluster.arrive.aligned;" ::: "memory");
        asm volatile("barrier.cluster.wait.aligned;" ::: "memory");

        // ---- pick cluster winner: depth-4 max tree over 16 slots ----
        {
            unsigned long long k[CLUSTER];
            int wc[CLUSTER];
#pragma unroll
            for (int c = 0; c < CLUSTER; ++c) { k[c] = s_key[p][c]; wc[c] = c; }
#pragma unroll
            for (int s = CLUSTER / 2; s >= 1; s >>= 1) {
#pragma unroll
                for (int i = 0; i < s; ++i) {
                    if (k[i + s] > k[i]) { k[i] = k[i + s]; wc[i] = wc[i + s]; }
                }
            }
            const float4 co = s_co[p][wc[0]];
            lx = co.x; ly = co.y; lz = co.z;
        }

        if (rank == 0 && tid == 0) {
            ob[j]              = lx;
            ob[NPOINT + j]     = ly;
            ob[2 * NPOINT + j] = lz;
        }
    }
}

extern "C" void kernel_launch(void* const* d_in, const int* in_sizes, int n_in,
                              void* d_out, int out_size)
{
    (void)in_sizes; (void)n_in; (void)out_size;
    const float* xyz_t = (const float*)d_in[1];   // points_xyz_t: (B, 3, N)
    float* out = (float*)d_out;                   // (B, 3, NPOINT)

    // Nonportable 16-CTA cluster. Host-side attribute + extended launch:
    // nothing enqueued except the kernel itself -> graph-capture safe,
    // deterministic, idempotent.
    cudaFuncSetAttribute(fps_cluster_kernel,
                         cudaFuncAttributeNonPortableClusterSizeAllowed, 1);

    const int dyn_bytes = 3 * PER_CTA * (int)sizeof(float);   // 24576

    cudaLaunchConfig_t cfg = {};
    cfg.gridDim  = dim3(BATCH * CLUSTER, 1, 1);
    cfg.blockDim = dim3(T, 1, 1);
    cfg.dynamicSmemBytes = dyn_bytes;
    cudaLaunchAttribute attrs[1];
    attrs[0].id = cudaLaunchAttributeClusterDimension;
    attrs[0].val.clusterDim.x = CLUSTER;
    attrs[0].val.clusterDim.y = 1;
    attrs[0].val.clusterDim.z = 1;
    cfg.attrs = attrs;
    cfg.numAttrs = 1;

    cudaLaunchKernelEx(&cfg, fps_cluster_kernel, xyz_t, out);
}

// round 8
// speedup vs baseline: 1.1658x; 1.1658x over previous
#include <cuda_runtime.h>
#include <cstdint>

// D-FPS (B=8, N=32768, npoint=2048) + gather xyz -> out (B,3,2048) fp32.
//
// 4 clusters x 8 CTAs (grid=32, 512 threads). Each cluster runs TWO
// independent FPS problems (batches 2c, 2c+1) in lockstep so the per-
// iteration cluster rendezvous + dissemination overhead is amortized over
// two batches. Each thread owns 8 points of EACH batch, packed f32x2 in
// registers; running-min temps in registers. Per iteration:
//   - 2x packed add/mul.rn.f32x2 distance updates (independent chains -> ILP)
//   - warp argmax via redux.sync per batch (float bits of v>=0 u32-monotone),
//     min-index tie-break == jnp.argmax first occurrence
//   - warp0 reduces batch0's 16 warp candidates, warp1 reduces batch1's, in
//     parallel; lanes 0..7 of each disseminate {key,x,y,z} to cluster CTA
//     dst==lane (mapa + st.shared::cluster); winner coords from CTA-local
//     smem coord tables (LDS, not L2)
//   - ONE barrier.cluster serves both batches (arrive releases remote stores)
//   - every thread picks both cluster winners from its own smem slots.
// Slots double-buffered by parity: same-parity overwrite for iter j+2 is
// issued only after the cluster barrier of iter j+1, which post-dates all
// reads of the iter-j slots.

constexpr int BATCH   = 8;
constexpr int NPTS    = 32768;
constexpr int NPOINT  = 2048;
constexpr int CLUSTER = 8;
constexpr int T       = 512;
constexpr int PER_CTA = NPTS / CLUSTER;  // 4096 per batch
constexpr int P       = PER_CTA / T;     // 8 points / thread / batch
constexpr int NPAIR   = P / 2;           // 4 packed pairs / batch
constexpr int NW      = T / 32;          // 16 warps

__device__ __forceinline__ uint32_t smem_u32(const void* p) {
    uint32_t a;
    asm("{ .reg .u64 t; cvta.to.shared.u64 t, %1; cvt.u32.u64 %0, t; }"
        : "=r"(a) : "l"(p));
    return a;
}

extern __shared__ float s_dyn[];  // [2 batches][3 planes][4096] = 96KB

__global__ __launch_bounds__(T, 1) __cluster_dims__(CLUSTER, 1, 1)
void fps_cluster_kernel(const float* __restrict__ xyz_t, float* __restrict__ out)
{
    const int cl = blockIdx.x >> 3;          // cluster id 0..3
    uint32_t rank;
    asm("mov.u32 %0, %%cluster_ctarank;" : "=r"(rank));

    const int tid = threadIdx.x;
    const int w = tid >> 5, l = tid & 31;
    const int pbase = (int)rank * PER_CTA;

    const float* __restrict__ base0 = xyz_t + (size_t)(2 * cl)     * 3 * NPTS;
    const float* __restrict__ base1 = xyz_t + (size_t)(2 * cl + 1) * 3 * NPTS;
    float* __restrict__ ob0 = out + (size_t)(2 * cl)     * 3 * NPOINT;
    float* __restrict__ ob1 = out + (size_t)(2 * cl + 1) * 3 * NPOINT;

    float* stab[2];
    stab[0] = s_dyn;                 // batch0: sx|sy|sz, 4096 each
    stab[1] = s_dyn + 3 * PER_CTA;   // batch1

    __shared__ uint32_t s_wv[2][NW], s_wi[2][NW];
    __shared__ unsigned long long s_key[2][2][CLUSTER];  // [parity][batch][src]
    __shared__ float4 s_co[2][2][CLUSTER];

    // ---- load coords: smem tables + packed registers ----
    unsigned long long xp[2][NPAIR], yp[2][NPAIR], zp[2][NPAIR];
    float tmp[2][P];
#pragma unroll
    for (int bb = 0; bb < 2; ++bb) {
        const float* xs = (bb ? base1 : base0);
        const float* ys = xs + NPTS;
        const float* zs = xs + 2 * NPTS;
        float a[P], c[P], d[P];
#pragma unroll
        for (int i = 0; i < P; ++i) {
            const int g = pbase + i * T + tid;
            a[i] = xs[g]; c[i] = ys[g]; d[i] = zs[g];
            stab[bb][              i * T + tid] = a[i];
            stab[bb][PER_CTA     + i * T + tid] = c[i];
            stab[bb][2 * PER_CTA + i * T + tid] = d[i];
            tmp[bb][i] = 1e10f;
        }
#pragma unroll
        for (int q = 0; q < NPAIR; ++q) {
            asm("mov.b64 %0, {%1, %2};" : "=l"(xp[bb][q]) : "f"(a[2*q]), "f"(a[2*q+1]));
            asm("mov.b64 %0, {%1, %2};" : "=l"(yp[bb][q]) : "f"(c[2*q]), "f"(c[2*q+1]));
            asm("mov.b64 %0, {%1, %2};" : "=l"(zp[bb][q]) : "f"(d[2*q]), "f"(d[2*q+1]));
        }
    }

    // idx[0] = 0 for both batches
    float lx0 = __ldg(base0),            ly0 = __ldg(base0 + NPTS),
          lz0 = __ldg(base0 + 2 * NPTS);
    float lx1 = __ldg(base1),            ly1 = __ldg(base1 + NPTS),
          lz1 = __ldg(base1 + 2 * NPTS);
    if (rank == 0 && tid == 0) {
        ob0[0] = lx0; ob0[NPOINT] = ly0; ob0[2 * NPOINT] = lz0;
        ob1[0] = lx1; ob1[NPOINT] = ly1; ob1[2 * NPOINT] = lz1;
    }

    for (int j = 1; j < NPOINT; ++j) {
        const float lxs[2] = {lx0, lx1}, lys[2] = {ly0, ly1}, lzs[2] = {lz0, lz1};
        uint32_t vmax[2], imin[2];

#pragma unroll
        for (int bb = 0; bb < 2; ++bb) {
            unsigned long long nlx2, nly2, nlz2;
            {
                const float nx = -lxs[bb], ny = -lys[bb], nz = -lzs[bb];
                asm("mov.b64 %0, {%1, %1};" : "=l"(nlx2) : "f"(nx));
                asm("mov.b64 %0, {%1, %1};" : "=l"(nly2) : "f"(ny));
                asm("mov.b64 %0, {%1, %1};" : "=l"(nlz2) : "f"(nz));
            }
            float bv = -1.0f;
            int   bs = 0;
#pragma unroll
            for (int q = 0; q < NPAIR; ++q) {
                unsigned long long dx, dy, dz, qx, qy, qz, s01, acc;
                asm("add.rn.f32x2 %0, %1, %2;" : "=l"(dx) : "l"(xp[bb][q]), "l"(nlx2));
                asm("add.rn.f32x2 %0, %1, %2;" : "=l"(dy) : "l"(yp[bb][q]), "l"(nly2));
                asm("add.rn.f32x2 %0, %1, %2;" : "=l"(dz) : "l"(zp[bb][q]), "l"(nlz2));
                asm("mul.rn.f32x2 %0, %1, %1;" : "=l"(qx) : "l"(dx));
                asm("mul.rn.f32x2 %0, %1, %1;" : "=l"(qy) : "l"(dy));
                asm("mul.rn.f32x2 %0, %1, %1;" : "=l"(qz) : "l"(dz));
                asm("add.rn.f32x2 %0, %1, %2;" : "=l"(s01) : "l"(qx), "l"(qy));
                asm("add.rn.f32x2 %0, %1, %2;" : "=l"(acc) : "l"(s01), "l"(qz));
                float d0, d1;
                asm("mov.b64 {%0, %1}, %2;" : "=f"(d0), "=f"(d1) : "l"(acc));
                float t0 = fminf(tmp[bb][2*q], d0);     tmp[bb][2*q] = t0;
                if (t0 > bv) { bv = t0; bs = 2*q; }
                float t1 = fminf(tmp[bb][2*q+1], d1);   tmp[bb][2*q+1] = t1;
                if (t1 > bv) { bv = t1; bs = 2*q+1; }
            }
            const uint32_t idx = (uint32_t)(pbase + bs * T + tid);
            const uint32_t vb = __float_as_uint(bv);
            vmax[bb] = __reduce_max_sync(0xffffffffu, vb);
            imin[bb] = __reduce_min_sync(0xffffffffu,
                           (vb == vmax[bb]) ? idx : 0xffffffffu);
        }
        if (l == 0) {
            s_wv[0][w] = vmax[0]; s_wi[0][w] = imin[0];
            s_wv[1][w] = vmax[1]; s_wi[1][w] = imin[1];
        }
        __syncthreads();

        const int p = j & 1;

        if (w < 2) {   // warp0 -> batch0, warp1 -> batch1 (parallel warps)
            const int bb = w;
            const uint32_t v  = (l < NW) ? s_wv[bb][l] : 0u;
            const uint32_t ii = (l < NW) ? s_wi[bb][l] : 0xffffffffu;
            const uint32_t vm = __reduce_max_sync(0xffffffffu, v);
            const uint32_t im = __reduce_min_sync(0xffffffffu,
                                    (v == vm) ? ii : 0xffffffffu);
            if (l < CLUSTER) {
                const int li = (int)im - pbase;          // in own range
                const float cx = stab[bb][li];
                const float cy = stab[bb][PER_CTA + li];
                const float cz = stab[bb][2 * PER_CTA + li];
                const unsigned long long key =
                    ((unsigned long long)vm << 32) | (uint32_t)(~im);
                unsigned long long xyp;
                asm("mov.b64 %0, {%1, %2};" : "=l"(xyp) : "f"(cx), "f"(cy));
                const uint32_t zb = __float_as_uint(cz);
                const uint32_t ka = smem_u32(&s_key[p][bb][rank]);
                const uint32_t ca = smem_u32(&s_co[p][bb][rank]);
                const int dco = (int)(ca - ka);
                uint32_t rk;
                asm volatile("mapa.shared::cluster.u32 %0, %1, %2;"
                             : "=r"(rk) : "r"(ka), "r"(l));
                asm volatile("st.shared::cluster.b64 [%0], %1;"
                             :: "r"(rk), "l"(key) : "memory");
                asm volatile("st.shared::cluster.b64 [%0], %1;"
                             :: "r"(rk + dco), "l"(xyp) : "memory");
                asm volatile("st.shared::cluster.b32 [%0+8], %1;"
                             :: "r"(rk + dco), "r"(zb) : "memory");
            }
        }

        // arrive = release (orders the shared::cluster stores), wait = acquire
        asm volatile("barrier.cluster.arrive.aligned;" ::: "memory");
        asm volatile("barrier.cluster.wait.aligned;" ::: "memory");

        // ---- pick both cluster winners locally ----
        {
            unsigned long long wk = s_key[p][0][0];
            int wc = 0;
#pragma unroll
            for (int c = 1; c < CLUSTER; ++c) {
                const unsigned long long kk = s_key[p][0][c];
                if (kk > wk) { wk = kk; wc = c; }
            }
            const float4 co = s_co[p][0][wc];
            lx0 = co.x; ly0 = co.y; lz0 = co.z;
        }
        {
            unsigned long long wk = s_key[p][1][0];
            int wc = 0;
#pragma unroll
            for (int c = 1; c < CLUSTER; ++c) {
                const unsigned long long kk = s_key[p][1][c];
                if (kk > wk) { wk = kk; wc = c; }
            }
            const float4 co = s_co[p][1][wc];
            lx1 = co.x; ly1 = co.y; lz1 = co.z;
        }

        if (rank == 0 && tid == 0) {
            ob0[j]              = lx0;
            ob0[NPOINT + j]     = ly0;
            ob0[2 * NPOINT + j] = lz0;
            ob1[j]              = lx1;
            ob1[NPOINT + j]     = ly1;
            ob1[2 * NPOINT + j] = lz1;
        }
    }
}

extern "C" void kernel_launch(void* const* d_in, const int* in_sizes, int n_in,
                              void* d_out, int out_size)
{
    (void)in_sizes; (void)n_in; (void)out_size;
    const float* xyz_t = (const float*)d_in[1];   // points_xyz_t: (B, 3, N)
    float* out = (float*)d_out;                   // (B, 3, NPOINT)

    // 96KB dynamic smem (two 48KB coord tables) -> opt-in. Host-side
    // attribute call: nothing enqueued, capture-safe, deterministic.
    const int dyn_bytes = 2 * 3 * PER_CTA * (int)sizeof(float);   // 98304
    cudaFuncSetAttribute(fps_cluster_kernel,
                         cudaFuncAttributeMaxDynamicSharedMemorySize, dyn_bytes);

    fps_cluster_kernel<<<(BATCH / 2) * CLUSTER, T, dyn_bytes>>>(xyz_t, out);
}